// round 1
// baseline (speedup 1.0000x reference)
#include <cuda_runtime.h>

// VQ nearest-codebook quantization.
// Inputs:  d_in[0] = z_e_x  [65536, 128] fp32 (4096*16 rows)
//          d_in[1] = codebook [1024, 128] fp32
// Outputs (fp32, concatenated in reference return order):
//   codes      [65536*128]
//   flat_idx   [65536]   (as float)
//   idx        [65536]   (same values, reshape only)
//   distances  [65536]

#define BM 128
#define BN 128
#define BK 8
#define TM 8
#define TN 8
#define C_DIM 128

#define ROWS_MAX 65536
#define CODES_MAX 1024

__device__ float g_xsq[ROWS_MAX];
__device__ float g_csq[CODES_MAX];

// One warp per row: sum of squares of 128 floats.
__global__ void xsq_kernel(const float* __restrict__ X) {
    int row = blockIdx.x * blockDim.y + threadIdx.y;
    float4 v = reinterpret_cast<const float4*>(X + (size_t)row * C_DIM)[threadIdx.x];
    float s = v.x * v.x + v.y * v.y + v.z * v.z + v.w * v.w;
    #pragma unroll
    for (int o = 16; o; o >>= 1) s += __shfl_xor_sync(0xffffffffu, s, o);
    if (threadIdx.x == 0) g_xsq[row] = s;
}

__global__ void csq_kernel(const float* __restrict__ CB) {
    int row = blockIdx.x * blockDim.y + threadIdx.y;
    float4 v = reinterpret_cast<const float4*>(CB + (size_t)row * C_DIM)[threadIdx.x];
    float s = v.x * v.x + v.y * v.y + v.z * v.z + v.w * v.w;
    #pragma unroll
    for (int o = 16; o; o >>= 1) s += __shfl_xor_sync(0xffffffffu, s, o);
    if (threadIdx.x == 0) g_csq[row] = s;
}

// Main kernel: per 128-row block, scan all 1024 codes with a 128x128x8
// register-tiled fp32 GEMM, tracking per-row argmin of (csq - 2*dot).
__global__ __launch_bounds__(256, 2)
void vq_kernel(const float* __restrict__ X, const float* __restrict__ CB,
               float* __restrict__ out_codes,
               float* __restrict__ out_fidx,
               float* __restrict__ out_idx,
               float* __restrict__ out_dist,
               int n_codes)
{
    __shared__ float As[BK][BM];
    __shared__ float Bs[BK][BN];
    __shared__ float rv[BM][16];
    __shared__ int   ri[BM][16];

    const int tid = threadIdx.x;
    const int tx = tid & 15;        // column group 0..15
    const int ty = tid >> 4;        // row group 0..15
    const int block_row = blockIdx.x * BM;

    float bestv[TM];
    int   besti[TM];
    #pragma unroll
    for (int i = 0; i < TM; i++) { bestv[i] = 3.4e38f; besti[i] = 0; }

    const int lr  = tid >> 1;           // 0..127, row within tile for loads
    const int lc4 = (tid & 1) * 4;      // 0 or 4, starting k-col for loads

    const int n_ctiles = n_codes / BN;

    for (int ct = 0; ct < n_ctiles; ct++) {
        float acc[TM][TN];
        #pragma unroll
        for (int i = 0; i < TM; i++)
            #pragma unroll
            for (int j = 0; j < TN; j++) acc[i][j] = 0.0f;

        #pragma unroll 1
        for (int k0 = 0; k0 < C_DIM; k0 += BK) {
            // Load A tile (transposed): rows block_row..+127, cols k0..k0+7
            {
                float4 va = *reinterpret_cast<const float4*>(
                    X + (size_t)(block_row + lr) * C_DIM + k0 + lc4);
                As[lc4 + 0][lr] = va.x;
                As[lc4 + 1][lr] = va.y;
                As[lc4 + 2][lr] = va.z;
                As[lc4 + 3][lr] = va.w;
                float4 vb = *reinterpret_cast<const float4*>(
                    CB + (size_t)(ct * BN + lr) * C_DIM + k0 + lc4);
                Bs[lc4 + 0][lr] = vb.x;
                Bs[lc4 + 1][lr] = vb.y;
                Bs[lc4 + 2][lr] = vb.z;
                Bs[lc4 + 3][lr] = vb.w;
            }
            __syncthreads();

            #pragma unroll
            for (int kk = 0; kk < BK; kk++) {
                float4 a0 = *reinterpret_cast<const float4*>(&As[kk][ty * TM]);
                float4 a1 = *reinterpret_cast<const float4*>(&As[kk][ty * TM + 4]);
                float4 b0 = *reinterpret_cast<const float4*>(&Bs[kk][tx * TN]);
                float4 b1 = *reinterpret_cast<const float4*>(&Bs[kk][tx * TN + 4]);
                float a[TM] = {a0.x, a0.y, a0.z, a0.w, a1.x, a1.y, a1.z, a1.w};
                float b[TN] = {b0.x, b0.y, b0.z, b0.w, b1.x, b1.y, b1.z, b1.w};
                #pragma unroll
                for (int i = 0; i < TM; i++)
                    #pragma unroll
                    for (int j = 0; j < TN; j++)
                        acc[i][j] += a[i] * b[j];
            }
            __syncthreads();
        }

        // Fold: score = csq - 2*dot; track running min (strict < keeps
        // earliest index; j ascending and ct ascending preserve
        // first-occurrence argmin semantics within a thread).
        #pragma unroll
        for (int j = 0; j < TN; j++) {
            int code = ct * BN + tx * TN + j;
            float cs = g_csq[code];
            #pragma unroll
            for (int i = 0; i < TM; i++) {
                float v = fmaf(-2.0f, acc[i][j], cs);
                if (v < bestv[i]) { bestv[i] = v; besti[i] = code; }
            }
        }
    }

    // Cross-thread reduction: 16 tx-threads cover each row.
    #pragma unroll
    for (int i = 0; i < TM; i++) {
        rv[ty * TM + i][tx] = bestv[i];
        ri[ty * TM + i][tx] = besti[i];
    }
    __syncthreads();

    if (tid < BM) {
        float bv = rv[tid][0];
        int   bi = ri[tid][0];
        #pragma unroll
        for (int t = 1; t < 16; t++) {
            float v = rv[tid][t];
            int   ii = ri[tid][t];
            // explicit tie-break: first (smallest) index wins
            if (v < bv || (v == bv && ii < bi)) { bv = v; bi = ii; }
        }
        int row = block_row + tid;
        if (out_fidx) {
            float fbi = (float)bi;
            out_fidx[row] = fbi;
            out_idx[row]  = fbi;
            out_dist[row] = g_xsq[row] + bv;
        }
        ri[tid][0] = bi;   // stash winning code for the gather
    }
    __syncthreads();

    // Codes gather: 2 threads per row, 64 floats (16 float4) each.
    {
        int r = tid >> 1;
        int half = tid & 1;
        int code = ri[r][0];
        const float4* src = reinterpret_cast<const float4*>(CB + (size_t)code * C_DIM) + half * 16;
        float4* dst = reinterpret_cast<float4*>(out_codes + (size_t)(block_row + r) * C_DIM) + half * 16;
        #pragma unroll
        for (int q = 0; q < 16; q++) dst[q] = src[q];
    }
}

extern "C" void kernel_launch(void* const* d_in, const int* in_sizes, int n_in,
                              void* d_out, int out_size)
{
    const float* X  = (const float*)d_in[0];
    const float* CB = (const float*)d_in[1];
    float* out = (float*)d_out;

    const int n_rows  = in_sizes[0] / C_DIM;   // 65536
    const int n_codes = in_sizes[1] / C_DIM;   // 1024

    // Output layout (fp32): codes | flat_idx | idx | distances
    size_t codes_n = (size_t)n_rows * C_DIM;
    bool extras = ((size_t)out_size >= codes_n + 3 * (size_t)n_rows);

    float* out_codes = out;
    float* out_fidx  = extras ? out + codes_n : nullptr;
    float* out_idx   = extras ? out + codes_n + n_rows : nullptr;
    float* out_dist  = extras ? out + codes_n + 2 * (size_t)n_rows : nullptr;

    // Precompute row norms (warp per row).
    xsq_kernel<<<n_rows / 8, dim3(32, 8)>>>(X);
    csq_kernel<<<n_codes / 8, dim3(32, 8)>>>(CB);

    vq_kernel<<<n_rows / BM, 256>>>(X, CB, out_codes, out_fidx, out_idx,
                                    out_dist, n_codes);
}